// round 14
// baseline (speedup 1.0000x reference)
#include <cuda_runtime.h>
#include <cuda_bf16.h>
#include <cstdint>

// inputs:  [B=32, 56, 56, C=256] fp32 ; routing: [32, 4] fp32
// out[b,h,w,j] = inputs[b,h,w, argmax(routing[b])*64 + j]  -> [32,56,56,64]
//
// R14: split-path kernel (LDG reads -> SMEM -> cp.async.bulk writes, 8.7us)
// restructured to a strictly ONE-WAVE grid: 784 CTAs x 2 tiles (32KB smem,
// 7 CTAs/SM by smem -> all 784 resident; previously 1568 CTAs ran 1.3 waves
// with a ~384-CTA tail). Per warp: two 2KB phases, each LDGx4 -> STSx4 ->
// syncwarp -> lane0 bulk-store commit; single wait_group 0 at the end so
// phase-1 loads overlap phase-0's store drain.

namespace {
constexpr int B       = 32;
constexpr int HW      = 56 * 56;      // 3136 pixels per batch
constexpr int ROUTES  = 4;
constexpr int V       = 16;           // float4 per output pixel (64 floats)
constexpr int CV      = 64;           // float4 per input pixel (256 floats)
constexpr int THREADS = 256;
constexpr int PHASES  = 2;
constexpr int PER_TH  = 4;            // float4 per thread per phase (MLP=4)
constexpr int PHASE_F4 = 32 * PER_TH;                     // 128 f4 = 2KB/warp
constexpr int WARP_F4  = PHASES * PHASE_F4;               // 256 f4 = 4KB/warp
constexpr int PER_BLK  = (THREADS / 32) * WARP_F4;        // 2048 f4 = 32KB
constexpr long long TOTAL_V4 = (long long)B * HW * V;     // 1,605,632
constexpr int BLOCKS  = (int)(TOTAL_V4 / PER_BLK);        // 784 (exact)
constexpr int PHASE_BYTES = PHASE_F4 * 16;                // 2048
// 50176 f4 per batch is an exact multiple of 128 -> each 128-f4 phase slice
// lies entirely within one batch.
}

__global__ __launch_bounds__(THREADS)
void routing_gather_kernel(const float4* __restrict__ in4,
                           const float*  __restrict__ routing,
                           float4* __restrict__ out4)
{
    __shared__ alignas(128) float4 tile[PER_BLK];   // 32 KB, = output layout

    const int warp = threadIdx.x >> 5;
    const int lane = threadIdx.x & 31;

#pragma unroll
    for (int p = 0; p < PHASES; ++p) {
        // This phase's contiguous 128-f4 output slice.
        const int slice0 = blockIdx.x * PER_BLK + warp * WARP_F4 + p * PHASE_F4;
        const int t0     = slice0 >> 4;             // first pixel of slice
        const int b      = t0 / HW;                 // const-divisor -> mulhi

        // argmax over 4 logits (uniform per slice; L1 broadcast).
        const float* r = routing + b * ROUTES;
        float best = r[0];
        int route = 0;
#pragma unroll
        for (int k = 1; k < ROUTES; ++k) {
            float v = r[k];
            if (v > best) { best = v; route = k; }  // strict > = first-max tie
        }
        const int rbase = route * V;

        // 4 independent coalesced LDG.128 (front-batched, MLP_p1=4).
        float4 v[PER_TH];
#pragma unroll
        for (int k = 0; k < PER_TH; ++k) {
            int idx = slice0 + lane + k * 32;       // output float4 index
            int t   = idx >> 4;                     // pixel index
            int j   = idx & (V - 1);                // float4 within pixel
            v[k] = __ldg(&in4[(long long)t * CV + rbase + j]);
        }

        // STS into the matching SMEM slice (output layout, conflict-free).
        const int sbase = warp * WARP_F4 + p * PHASE_F4 + lane;
#pragma unroll
        for (int k = 0; k < PER_TH; ++k) {
            tile[sbase + k * 32] = v[k];
        }
        __syncwarp();

        // Commit this phase's 2KB bulk store; don't wait yet.
        if (lane == 0) {
            uint32_t st = (uint32_t)__cvta_generic_to_shared(
                &tile[warp * WARP_F4 + p * PHASE_F4]);
            float4* dst = out4 + slice0;
            asm volatile("fence.proxy.async.shared::cta;" ::: "memory");
            asm volatile("cp.async.bulk.global.shared::cta.bulk_group [%0], [%1], %2;"
                         :: "l"(dst), "r"(st), "r"(PHASE_BYTES) : "memory");
            asm volatile("cp.async.bulk.commit_group;" ::: "memory");
        }
    }

    // Drain all committed bulk stores before CTA exit (SMEM must stay live).
    if (lane == 0) {
        asm volatile("cp.async.bulk.wait_group 0;" ::: "memory");
    }
}

extern "C" void kernel_launch(void* const* d_in, const int* in_sizes, int n_in,
                              void* d_out, int out_size)
{
    const float4* in4     = (const float4*)d_in[0];
    const float*  routing = (const float*)d_in[1];
    float4*       out4    = (float4*)d_out;

    routing_gather_kernel<<<BLOCKS, THREADS>>>(in4, routing, out4);
}

// round 15
// speedup vs baseline: 1.3801x; 1.3801x over previous
#include <cuda_runtime.h>
#include <cuda_bf16.h>
#include <cstdint>

// inputs:  [B=32, 56, 56, C=256] fp32 ; routing: [32, 4] fp32
// out[b,h,w,j] = inputs[b,h,w, argmax(routing[b])*64 + j]  -> [32,56,56,64]
//
// R15 = R12 (best, 8.7us: LDG reads -> SMEM tile -> one 16KB cp.async.bulk
// store per CTA) with ONE change: reads use __ldcg (L2-only, no L1 fill).
// L1D and SMEM share the unified array on sm_103a; skipping the zero-reuse
// L1 fills removes ~25.7MB of L1-array writes competing with the STS stream.
// (R14's one-wave/phased variant regressed 8.7->15.1: fewer in-flight reads
// + per-phase fence serialization. Reverted.)

namespace {
constexpr int B       = 32;
constexpr int HW      = 56 * 56;      // 3136 pixels per batch
constexpr int ROUTES  = 4;
constexpr int V       = 16;           // float4 per output pixel (64 floats)
constexpr int CV      = 64;           // float4 per input pixel (256 floats)
constexpr int THREADS = 256;
constexpr int PER_TH  = 4;            // float4 per thread (MLP=4)
constexpr int PER_BLK = THREADS * PER_TH;                 // 1024 f4 = 16 KB
constexpr long long TOTAL_V4 = (long long)B * HW * V;     // 1,605,632
constexpr int BLOCKS  = (int)(TOTAL_V4 / PER_BLK);        // 1568 (exact)
constexpr int BLOCKS_PER_BATCH = BLOCKS / B;              // 49   (exact)
constexpr int TILE_BYTES = PER_BLK * 16;                  // 16384
}

__global__ __launch_bounds__(THREADS)
void routing_gather_kernel(const float4* __restrict__ in4,
                           const float*  __restrict__ routing,
                           float4* __restrict__ out4)
{
    __shared__ alignas(128) float4 tile[PER_BLK];   // 16 KB, = output layout

    const int b = blockIdx.x / BLOCKS_PER_BATCH;    // const-divisor -> mulhi

    // argmax over 4 logits; uniform address across block -> broadcast.
    const float* r = routing + b * ROUTES;
    float best = r[0];
    int route = 0;
#pragma unroll
    for (int k = 1; k < ROUTES; ++k) {
        float v = r[k];
        if (v > best) { best = v; route = k; }      // strict > = first-max tie
    }
    const int rbase = route * V;

    // Warp-coalesced: warp owns 128 consecutive f4, lane-stride 32.
    const int local = (threadIdx.x >> 5) * (32 * PER_TH) + (threadIdx.x & 31);
    const int base  = blockIdx.x * PER_BLK + local;

    // 4 independent coalesced loads, L2-only (no L1 fill; zero reuse).
    float4 v[PER_TH];
#pragma unroll
    for (int k = 0; k < PER_TH; ++k) {
        int idx = base + k * 32;          // global output float4 index
        int t   = idx >> 4;               // pixel index (b*HW + pix)
        int j   = idx & (V - 1);          // float4 within pixel
        v[k] = __ldcg(&in4[(long long)t * CV + rbase + j]);
    }
#pragma unroll
    for (int k = 0; k < PER_TH; ++k) {
        tile[local + k * 32] = v[k];
    }
    __syncthreads();

    // One bulk async store per CTA: 16KB SMEM -> GMEM via the copy engine.
    if (threadIdx.x == 0) {
        uint32_t st = (uint32_t)__cvta_generic_to_shared(tile);
        float4* dst = out4 + (long long)blockIdx.x * PER_BLK;
        asm volatile("fence.proxy.async.shared::cta;" ::: "memory");
        asm volatile("cp.async.bulk.global.shared::cta.bulk_group [%0], [%1], %2;"
                     :: "l"(dst), "r"(st), "r"(TILE_BYTES) : "memory");
        asm volatile("cp.async.bulk.commit_group;" ::: "memory");
        asm volatile("cp.async.bulk.wait_group 0;" ::: "memory");
    }
}

extern "C" void kernel_launch(void* const* d_in, const int* in_sizes, int n_in,
                              void* d_out, int out_size)
{
    const float4* in4     = (const float4*)d_in[0];
    const float*  routing = (const float*)d_in[1];
    float4*       out4    = (float4*)d_out;

    routing_gather_kernel<<<BLOCKS, THREADS>>>(in4, routing, out4);
}

// round 16
// speedup vs baseline: 1.7417x; 1.2620x over previous
#include <cuda_runtime.h>
#include <cuda_bf16.h>
#include <cstdint>

// inputs:  [B=32, 56, 56, C=256] fp32 ; routing: [32, 4] fp32
// out[b,h,w,j] = inputs[b,h,w, argmax(routing[b])*64 + j]  -> [32,56,56,64]
//
// R16 = R12 (best, 8.7us: __ldg reads -> SMEM tile -> one 16KB cp.async.bulk
// store per CTA) + ONE change: the bulk store carries an L2::evict_first
// cache policy. Output lines are write-allocate garbage (never read); marking
// them evict-first stops them competing with the L2-resident input and
// smooths the writeback drain. (R15 proved __ldcg < __ldg here: reverted.)

namespace {
constexpr int B       = 32;
constexpr int HW      = 56 * 56;      // 3136 pixels per batch
constexpr int ROUTES  = 4;
constexpr int V       = 16;           // float4 per output pixel (64 floats)
constexpr int CV      = 64;           // float4 per input pixel (256 floats)
constexpr int THREADS = 256;
constexpr int PER_TH  = 4;            // float4 per thread (MLP=4)
constexpr int PER_BLK = THREADS * PER_TH;                 // 1024 f4 = 16 KB
constexpr long long TOTAL_V4 = (long long)B * HW * V;     // 1,605,632
constexpr int BLOCKS  = (int)(TOTAL_V4 / PER_BLK);        // 1568 (exact)
constexpr int BLOCKS_PER_BATCH = BLOCKS / B;              // 49   (exact)
constexpr int TILE_BYTES = PER_BLK * 16;                  // 16384
}

__global__ __launch_bounds__(THREADS)
void routing_gather_kernel(const float4* __restrict__ in4,
                           const float*  __restrict__ routing,
                           float4* __restrict__ out4)
{
    __shared__ alignas(128) float4 tile[PER_BLK];   // 16 KB, = output layout

    const int b = blockIdx.x / BLOCKS_PER_BATCH;    // const-divisor -> mulhi

    // argmax over 4 logits; uniform address across block -> broadcast.
    const float* r = routing + b * ROUTES;
    float best = r[0];
    int route = 0;
#pragma unroll
    for (int k = 1; k < ROUTES; ++k) {
        float v = r[k];
        if (v > best) { best = v; route = k; }      // strict > = first-max tie
    }
    const int rbase = route * V;

    // Warp-coalesced: warp owns 128 consecutive f4, lane-stride 32.
    const int local = (threadIdx.x >> 5) * (32 * PER_TH) + (threadIdx.x & 31);
    const int base  = blockIdx.x * PER_BLK + local;

    // 4 independent coalesced LDG.128 via __ldg (.nc path — proven fastest).
    float4 v[PER_TH];
#pragma unroll
    for (int k = 0; k < PER_TH; ++k) {
        int idx = base + k * 32;          // global output float4 index
        int t   = idx >> 4;               // pixel index (b*HW + pix)
        int j   = idx & (V - 1);          // float4 within pixel
        v[k] = __ldg(&in4[(long long)t * CV + rbase + j]);
    }
#pragma unroll
    for (int k = 0; k < PER_TH; ++k) {
        tile[local + k * 32] = v[k];
    }
    __syncthreads();

    // One bulk async store per CTA, output lines marked L2 evict-first.
    if (threadIdx.x == 0) {
        uint32_t st = (uint32_t)__cvta_generic_to_shared(tile);
        float4* dst = out4 + (long long)blockIdx.x * PER_BLK;
        uint64_t policy;
        asm volatile("createpolicy.fractional.L2::evict_first.b64 %0, 1.0;"
                     : "=l"(policy));
        asm volatile("fence.proxy.async.shared::cta;" ::: "memory");
        asm volatile(
            "cp.async.bulk.global.shared::cta.bulk_group.L2::cache_hint "
            "[%0], [%1], %2, %3;"
            :: "l"(dst), "r"(st), "r"(TILE_BYTES), "l"(policy) : "memory");
        asm volatile("cp.async.bulk.commit_group;" ::: "memory");
        asm volatile("cp.async.bulk.wait_group 0;" ::: "memory");
    }
}

extern "C" void kernel_launch(void* const* d_in, const int* in_sizes, int n_in,
                              void* d_out, int out_size)
{
    const float4* in4     = (const float4*)d_in[0];
    const float*  routing = (const float*)d_in[1];
    float4*       out4    = (float4*)d_out;

    routing_gather_kernel<<<BLOCKS, THREADS>>>(in4, routing, out4);
}